// round 15
// baseline (speedup 1.0000x reference)
#include <cuda_runtime.h>
#include <cuda_fp16.h>
#include <math.h>
#include <stdint.h>

#define N_NODES 100000
#define IN_FEAT 128
#define HIDDEN  256
#define N_TILES 1563   // ceil(100000/64)

// ---------------- scratch (static device globals) ----------------
__device__ float  g_agg1[(size_t)N_NODES * IN_FEAT];    // 51.2 MB
__device__ float  g_cnt [N_NODES];
__device__ float2 g_zl  [N_NODES];
__device__ float2 g_zr  [N_NODES];
__device__ float2 g_agg2s[N_NODES];
__device__ __half g_Whf[256 * 256];                     // W[n=256][k=256] fp16

// ---------------- helpers ----------------
__device__ __forceinline__ uint32_t smem_u32(const void* p) {
    uint32_t a;
    asm("{ .reg .u64 t; cvta.to.shared.u64 t, %1; cvt.u32.u64 %0, t; }" : "=r"(a) : "l"(p));
    return a;
}
__device__ __forceinline__ void ldsm_x4(uint32_t* r, uint32_t addr) {
    asm volatile("ldmatrix.sync.aligned.m8n8.x4.shared.b16 {%0,%1,%2,%3}, [%4];"
                 : "=r"(r[0]), "=r"(r[1]), "=r"(r[2]), "=r"(r[3]) : "r"(addr));
}
__device__ __forceinline__ void mma_f16(float* d, const uint32_t* a, uint32_t b0, uint32_t b1) {
    asm volatile("mma.sync.aligned.m16n8k16.row.col.f32.f16.f16.f32 "
                 "{%0,%1,%2,%3}, {%4,%5,%6,%7}, {%8,%9}, {%0,%1,%2,%3};"
                 : "+f"(d[0]), "+f"(d[1]), "+f"(d[2]), "+f"(d[3])
                 : "r"(a[0]), "r"(a[1]), "r"(a[2]), "r"(a[3]), "r"(b0), "r"(b1));
}
__device__ __forceinline__ void cp16(uint32_t sm, const void* g) {
    asm volatile("cp.async.cg.shared.global [%0], [%1], 16;" :: "r"(sm), "l"(g));
}
#define CP_COMMIT() asm volatile("cp.async.commit_group;" ::: "memory")
#define CP_WAIT0()  asm volatile("cp.async.wait_group 0;" ::: "memory")

// SMEM layout: A resident (8 chunks), B double-buffered, 80B-padded rows
#define A_CH(c)     ((uint32_t)(c) * 5120u)             // 64 rows * 80B per chunk
#define BH_OFF(st)  (40960u + (st) * 20480u)            // 256*80
#define OFF_W2   81920u    // 4*256 f32
#define OFF_B1   86016u    // 256 f32
#define OFF_NORM 87040u    // 64 f32
#define OFF_Z    87296u    // 64*4 f32
#define OFF_INV  88320u    // 64 f32
#define SMEM_DYN 88576

// ---------------- small kernels ----------------
__global__ void k_zero() {
    const size_t n1 = (size_t)N_NODES * IN_FEAT;
    size_t stride = (size_t)gridDim.x * blockDim.x;
    size_t i0 = (size_t)blockIdx.x * blockDim.x + threadIdx.x;
    float4 z4 = make_float4(0.f, 0.f, 0.f, 0.f);
    for (size_t i = i0; i < n1 / 4; i += stride) ((float4*)g_agg1)[i] = z4;
    for (size_t i = i0; i < N_NODES; i += stride) {
        g_cnt[i] = 0.0f;
        g_agg2s[i] = make_float2(0.f, 0.f);
    }
}

__global__ void k_Whalf(const float* __restrict__ W1l, const float* __restrict__ W1r) {
    int idx = blockIdx.x * blockDim.x + threadIdx.x;   // 0..65535
    if (idx >= 256 * 256) return;
    int h = idx >> 8, k = idx & 255;
    float v = (k < 128) ? W1l[h * 128 + k] : W1r[h * 128 + (k - 128)];
    g_Whf[idx] = __float2half(v);
}

__global__ void k_scatter1(const float* __restrict__ x,
                           const int* __restrict__ src,
                           const int* __restrict__ dst, int E) {
    int gw   = (blockIdx.x * blockDim.x + threadIdx.x) >> 5;
    int lane = threadIdx.x & 31;
    if (gw >= E) return;
    int s = src[gw];
    int d = dst[gw];
    float4 v = ((const float4*)(x + (size_t)s * IN_FEAT))[lane];
    float* o = g_agg1 + (size_t)d * IN_FEAT + lane * 4;
    asm volatile("red.global.add.v4.f32 [%0], {%1, %2, %3, %4};"
                 :: "l"(o), "f"(v.x), "f"(v.y), "f"(v.z), "f"(v.w) : "memory");
    if (lane == 0)
        asm volatile("red.global.add.f32 [%0], %1;"
                     :: "l"(&g_cnt[d]), "f"(1.0f) : "memory");
}

// ---------------- HMMA GEMM: fp16 single-term, A tile-resident, M=64 x N=256 ----------------
__global__ void __launch_bounds__(256, 2) k_gemm(const float* __restrict__ x,
                                                 const float* __restrict__ b1,
                                                 const float* __restrict__ W2l,
                                                 const float* __restrict__ W2r) {
    extern __shared__ char smem[];
    const int t    = threadIdx.x;
    const int lane = t & 31;
    const int wid  = t >> 5;
    const int wm   = wid >> 2;        // 0..1 (m strip of 32)
    const int wn   = wid & 3;         // 0..3 (n strip of 64)
    const int n0   = blockIdx.x * 64;

    float* sW2   = (float*)(smem + OFF_W2);
    float* sB1   = (float*)(smem + OFF_B1);
    float* sNorm = (float*)(smem + OFF_NORM);
    float* sZ    = (float*)(smem + OFF_Z);
    float* sInv  = (float*)(smem + OFF_INV);

    const uint32_t smb = smem_u32(smem);

    sB1[t] = b1[t];
    for (int i = t; i < 1024; i += 256) {
        int m = i >> 8, k = i & 255;
        sW2[i] = (m < 2) ? W2l[m * 256 + k] : W2r[(m - 2) * 256 + k];
    }
    if (t < 64) {
        int n = n0 + t;
        sInv[t] = (n < N_NODES) ? (1.0f / fmaxf(g_cnt[n], 1.0f)) : 0.0f;
        sNorm[t] = 0.f;
        ((float4*)sZ)[t] = make_float4(0.f, 0.f, 0.f, 0.f);
    }

    // ---- issue B stage 0 copy early (overlaps A slab load) ----
    const int bbr = t >> 2;              // 0..63 (+64/128/192)
    const int bbc = t & 3;
    auto issueB = [&](int kc, uint32_t bh_off) {
#pragma unroll
        for (int i = 0; i < 4; i++) {
            int br = bbr + i * 64;
            uint32_t doff = (uint32_t)(br * 80 + bbc * 16);
            cp16(smb + bh_off + doff, g_Whf + (size_t)br * 256 + kc + bbc * 8);
        }
    };
    issueB(0, BH_OFF(0));
    CP_COMMIT();
    __syncthreads();   // sInv visible before A conversion

    // ---- load entire A slab (64 rows x 256 fp32), convert to fp16, store by chunk ----
    // thread t + i*256: row = idx>>6, c4 = (idx&63)*4; 64 consecutive threads = 1 row (coalesced)
#pragma unroll
    for (int i = 0; i < 16; i++) {
        int idx = t + i * 256;            // 0..4095
        int row = idx >> 6;               // 0..63
        int c4  = (idx & 63) * 4;         // 0..252
        int n   = n0 + row;
        float4 v = make_float4(0.f, 0.f, 0.f, 0.f);
        if (n < N_NODES) {
            if (c4 < 128) {
                v = *(const float4*)(g_agg1 + (size_t)n * 128 + c4);
                float iv = sInv[row];
                v.x *= iv; v.y *= iv; v.z *= iv; v.w *= iv;
            } else {
                v = *(const float4*)(x + (size_t)n * 128 + (c4 - 128));
            }
        }
        __half2 p0 = __halves2half2(__float2half(v.x), __float2half(v.y));
        __half2 p1 = __halves2half2(__float2half(v.z), __float2half(v.w));
        uint2 u; u.x = *(uint32_t*)&p0; u.y = *(uint32_t*)&p1;
        int chunk = c4 >> 5;
        uint32_t dst = A_CH(chunk) + (uint32_t)(row * 80 + (c4 & 31) * 2);
        *(uint2*)(smem + dst) = u;
    }
    CP_WAIT0();
    __syncthreads();

    // ---- per-warp ldsm bases ----
    const uint32_t rowo = (lane & 7) + ((lane >> 3) & 1) * 8;
    const uint32_t kB   = (lane >> 4) * 16;
    const uint32_t aBase = smb + (wm * 32 + rowo) * 80 + kB;
    const uint32_t bBase = smb + (wn * 64 + rowo) * 80 + kB;

    float acc[2][8][4];
#pragma unroll
    for (int a = 0; a < 2; a++)
#pragma unroll
        for (int b = 0; b < 8; b++)
#pragma unroll
            for (int c = 0; c < 4; c++) acc[a][b][c] = 0.f;

    auto compute = [&](int c, uint32_t bh_off) {
        const uint32_t aOff = A_CH(c);
#pragma unroll
        for (int s = 0; s < 2; s++) {
            const uint32_t so = s * 32;
            uint32_t ah[2][4];
            ldsm_x4(ah[0], aBase + aOff + so);
            ldsm_x4(ah[1], aBase + aOff + 16 * 80 + so);
            uint32_t bh[4][4];
#pragma unroll
            for (int tp = 0; tp < 4; tp++)
                ldsm_x4(bh[tp], bBase + tp * (16 * 80) + so + bh_off);

#pragma unroll
            for (int tp = 0; tp < 4; tp++)
#pragma unroll
                for (int tm = 0; tm < 2; tm++) {
                    mma_f16(acc[tm][2 * tp],     ah[tm], bh[tp][0], bh[tp][2]);
                    mma_f16(acc[tm][2 * tp + 1], ah[tm], bh[tp][1], bh[tp][3]);
                }
        }
    };

    // ---- main loop: 8 chunks, B double-buffered, A resident ----
#pragma unroll
    for (int kci = 0; kci < 8; kci++) {
        const uint32_t cur = kci & 1, nxt = cur ^ 1;
        if (kci < 7) {
            issueB((kci + 1) * 32, BH_OFF(nxt));
            CP_COMMIT();
        }
        compute(kci, BH_OFF(cur));
        if (kci < 7) CP_WAIT0();
        __syncthreads();
    }

    // ---- epilogue ----
#pragma unroll
    for (int tm = 0; tm < 2; tm++) {
        float s0 = 0.f, s1 = 0.f;
#pragma unroll
        for (int tn = 0; tn < 8; tn++) {
            int c0 = wn * 64 + tn * 8 + (lane & 3) * 2;
            float b0v = sB1[c0], b1v = sB1[c0 + 1];
            acc[tm][tn][0] += b0v;
            acc[tm][tn][1] += b1v;
            acc[tm][tn][2] += b0v;
            acc[tm][tn][3] += b1v;
            s0 += acc[tm][tn][0] * acc[tm][tn][0] + acc[tm][tn][1] * acc[tm][tn][1];
            s1 += acc[tm][tn][2] * acc[tm][tn][2] + acc[tm][tn][3] * acc[tm][tn][3];
        }
        s0 += __shfl_xor_sync(0xffffffffu, s0, 1);
        s0 += __shfl_xor_sync(0xffffffffu, s0, 2);
        s1 += __shfl_xor_sync(0xffffffffu, s1, 1);
        s1 += __shfl_xor_sync(0xffffffffu, s1, 2);
        if ((lane & 3) == 0) {
            int r = wm * 32 + tm * 16 + (lane >> 2);
            atomicAdd(&sNorm[r], s0);
            atomicAdd(&sNorm[r + 8], s1);
        }
    }
    __syncthreads();
    if (t < 64) sNorm[t] = 1.0f / fmaxf(sqrtf(sNorm[t]), 1e-12f);
    __syncthreads();

#pragma unroll
    for (int tm = 0; tm < 2; tm++) {
        int rbase = wm * 32 + tm * 16 + (lane >> 2);
        float rc0 = sNorm[rbase], rc1 = sNorm[rbase + 8];
        float d0[4] = {0.f, 0.f, 0.f, 0.f};
        float d1[4] = {0.f, 0.f, 0.f, 0.f};
#pragma unroll
        for (int tn = 0; tn < 8; tn++) {
            int c0 = wn * 64 + tn * 8 + (lane & 3) * 2;
            float h00 = fmaxf(acc[tm][tn][0] * rc0, 0.f);
            float h01 = fmaxf(acc[tm][tn][1] * rc0, 0.f);
            float h10 = fmaxf(acc[tm][tn][2] * rc1, 0.f);
            float h11 = fmaxf(acc[tm][tn][3] * rc1, 0.f);
#pragma unroll
            for (int o = 0; o < 4; o++) {
                float w0 = sW2[o * 256 + c0], w1 = sW2[o * 256 + c0 + 1];
                d0[o] += h00 * w0 + h01 * w1;
                d1[o] += h10 * w0 + h11 * w1;
            }
        }
#pragma unroll
        for (int o = 0; o < 4; o++) {
            d0[o] += __shfl_xor_sync(0xffffffffu, d0[o], 1);
            d0[o] += __shfl_xor_sync(0xffffffffu, d0[o], 2);
            d1[o] += __shfl_xor_sync(0xffffffffu, d1[o], 1);
            d1[o] += __shfl_xor_sync(0xffffffffu, d1[o], 2);
        }
        if ((lane & 3) == 0) {
#pragma unroll
            for (int o = 0; o < 4; o++) {
                atomicAdd(&sZ[rbase * 4 + o], d0[o]);
                atomicAdd(&sZ[(rbase + 8) * 4 + o], d1[o]);
            }
        }
    }
    __syncthreads();
    if (t < 64) {
        int n = n0 + t;
        if (n < N_NODES) {
            g_zl[n] = make_float2(sZ[t * 4 + 0], sZ[t * 4 + 1]);
            g_zr[n] = make_float2(sZ[t * 4 + 2], sZ[t * 4 + 3]);
        }
    }
}

// ---------------- scatter layer 2 + final ----------------
__global__ void k_scatter2(const int* __restrict__ src,
                           const int* __restrict__ dst, int E) {
    int e = blockIdx.x * blockDim.x + threadIdx.x;
    if (e >= E) return;
    int s = src[e];
    int d = dst[e];
    float2 z = g_zl[s];
    asm volatile("red.global.add.v2.f32 [%0], {%1, %2};"
                 :: "l"(&g_agg2s[d]), "f"(z.x), "f"(z.y) : "memory");
}

__global__ void k_final(const float* __restrict__ b2, float* __restrict__ out) {
    int n = blockIdx.x * blockDim.x + threadIdx.x;
    if (n >= N_NODES) return;
    float inv = 1.0f / fmaxf(g_cnt[n], 1.0f);
    float2 a = g_agg2s[n];
    float2 r = g_zr[n];
    float v0 = a.x * inv + r.x + b2[0];
    float v1 = a.y * inv + r.y + b2[1];
    float s = 1.0f / fmaxf(sqrtf(v0 * v0 + v1 * v1), 1e-12f);
    v0 *= s; v1 *= s;
    float m = fmaxf(v0, v1);
    float l = m + logf(expf(v0 - m) + expf(v1 - m));
    out[(size_t)n * 2 + 0] = v0 - l;
    out[(size_t)n * 2 + 1] = v1 - l;
}

extern "C" void kernel_launch(void* const* d_in, const int* in_sizes, int n_in,
                              void* d_out, int out_size) {
    const float* x   = (const float*)d_in[0];
    const int*   ei  = (const int*)d_in[1];
    const float* W1l = (const float*)d_in[2];
    const float* b1  = (const float*)d_in[3];
    const float* W1r = (const float*)d_in[4];
    const float* W2l = (const float*)d_in[5];
    const float* b2  = (const float*)d_in[6];
    const float* W2r = (const float*)d_in[7];
    float*       out = (float*)d_out;

    int E = in_sizes[1] / 2;
    const int* src = ei;
    const int* dst = ei + E;

    cudaFuncSetAttribute(k_gemm, cudaFuncAttributeMaxDynamicSharedMemorySize, SMEM_DYN);

    k_zero<<<592, 256>>>();
    k_Whalf<<<256, 256>>>(W1l, W1r);
    k_scatter1<<<(E * 32 + 255) / 256, 256>>>(x, src, dst, E);
    k_gemm<<<N_TILES, 256, SMEM_DYN>>>(x, b1, W2l, W2r);
    k_scatter2<<<(E + 255) / 256, 256>>>(src, dst, E);
    k_final<<<(N_NODES + 255) / 256, 256>>>(b2, out);
}

// round 16
// speedup vs baseline: 1.4537x; 1.4537x over previous
#include <cuda_runtime.h>
#include <cuda_fp16.h>
#include <math.h>
#include <stdint.h>

#define N_NODES 100000
#define N_PAD   100032
#define E_MAX   600000
#define N_TILES 1563   // ceil(100000/64)
#define NBLK    391    // ceil(100000/256)

// ---------------- scratch (static device globals) ----------------
__device__ int    g_cnt_i[N_NODES];
__device__ int    g_fill [N_NODES];
__device__ int    g_rs   [N_NODES + 1];
__device__ int    g_csr  [E_MAX];
__device__ int    g_bsum [512];
__device__ float2 g_zl   [N_NODES];
__device__ float2 g_zr   [N_NODES];
__device__ float2 g_agg2s[N_NODES];
__device__ __half g_xh  [(size_t)N_PAD * 128];   // x in fp16 (pad rows stay 0)
__device__ __half g_aggh[(size_t)N_PAD * 128];   // mean-agg * inv, fp16
__device__ __half g_Whf [256 * 256];             // W[n=256][k=256] fp16

// ---------------- helpers ----------------
__device__ __forceinline__ uint32_t smem_u32(const void* p) {
    uint32_t a;
    asm("{ .reg .u64 t; cvta.to.shared.u64 t, %1; cvt.u32.u64 %0, t; }" : "=r"(a) : "l"(p));
    return a;
}
__device__ __forceinline__ void ldsm_x4(uint32_t* r, uint32_t addr) {
    asm volatile("ldmatrix.sync.aligned.m8n8.x4.shared.b16 {%0,%1,%2,%3}, [%4];"
                 : "=r"(r[0]), "=r"(r[1]), "=r"(r[2]), "=r"(r[3]) : "r"(addr));
}
__device__ __forceinline__ void mma_f16(float* d, const uint32_t* a, uint32_t b0, uint32_t b1) {
    asm volatile("mma.sync.aligned.m16n8k16.row.col.f32.f16.f16.f32 "
                 "{%0,%1,%2,%3}, {%4,%5,%6,%7}, {%8,%9}, {%0,%1,%2,%3};"
                 : "+f"(d[0]), "+f"(d[1]), "+f"(d[2]), "+f"(d[3])
                 : "r"(a[0]), "r"(a[1]), "r"(a[2]), "r"(a[3]), "r"(b0), "r"(b1));
}
__device__ __forceinline__ void cp16(uint32_t sm, const void* g) {
    asm volatile("cp.async.cg.shared.global [%0], [%1], 16;" :: "r"(sm), "l"(g));
}
#define CP_COMMIT() asm volatile("cp.async.commit_group;" ::: "memory")
#define CP_WAIT0()  asm volatile("cp.async.wait_group 0;" ::: "memory")

// SMEM layout: A+B double-buffered (80B-padded rows), M-tile=64
#define AH_OFF(st)  ((st) * 5120u)                      // 64*80
#define BH_OFF(st)  (10240u + (st) * 20480u)            // 256*80
#define OFF_W2   51200u    // 4*256 f32
#define OFF_B1   55296u    // 256 f32
#define OFF_NORM 56320u    // 64 f32
#define OFF_Z    56576u    // 64*4 f32
#define SMEM_DYN 57600

// ---------------- prep kernels ----------------
__global__ void k_zero0() {
    int i = blockIdx.x * blockDim.x + threadIdx.x;
    int stride = gridDim.x * blockDim.x;
    for (int n = i; n < N_NODES; n += stride) {
        g_cnt_i[n] = 0;
        g_fill[n] = 0;
        g_agg2s[n] = make_float2(0.f, 0.f);
    }
}

// x -> fp16, W -> fp16
__global__ void k_prep(const float* __restrict__ x,
                       const float* __restrict__ W1l, const float* __restrict__ W1r) {
    int i = blockIdx.x * blockDim.x + threadIdx.x;
    int stride = gridDim.x * blockDim.x;
    const int XQ = N_NODES * 32;         // 3.2M float4
    for (int q = i; q < XQ; q += stride) {
        float4 v = ((const float4*)x)[q];
        __half2 p0 = __halves2half2(__float2half(v.x), __float2half(v.y));
        __half2 p1 = __halves2half2(__float2half(v.z), __float2half(v.w));
        uint2 u; u.x = *(uint32_t*)&p0; u.y = *(uint32_t*)&p1;
        ((uint2*)g_xh)[q] = u;
    }
    for (int q = i; q < 256 * 256; q += stride) {
        int h = q >> 8, k = q & 255;
        float v = (k < 128) ? W1l[h * 128 + k] : W1r[h * 128 + (k - 128)];
        g_Whf[q] = __float2half(v);
    }
}

__global__ void k_count(const int* __restrict__ dst, int E) {
    int e = blockIdx.x * blockDim.x + threadIdx.x;
    if (e < E) atomicAdd(&g_cnt_i[dst[e]], 1);
}

__global__ void k_scan1() {
    __shared__ int sh[256];
    int t = threadIdx.x;
    int i = blockIdx.x * 256 + t;
    sh[t] = (i < N_NODES) ? g_cnt_i[i] : 0;
    __syncthreads();
    for (int o = 128; o > 0; o >>= 1) {
        if (t < o) sh[t] += sh[t + o];
        __syncthreads();
    }
    if (t == 0) g_bsum[blockIdx.x] = sh[0];
}

__global__ void k_scan2() {
    __shared__ int sh[512];
    int t = threadIdx.x;
    int v = (t < NBLK) ? g_bsum[t] : 0;
    sh[t] = v;
    __syncthreads();
    for (int o = 1; o < 512; o <<= 1) {
        int tmp = (t >= o) ? sh[t - o] : 0;
        __syncthreads();
        sh[t] += tmp;
        __syncthreads();
    }
    if (t < NBLK) g_bsum[t] = sh[t] - v;   // exclusive
    if (t == NBLK - 1) g_rs[N_NODES] = sh[t];
}

__global__ void k_scan3() {
    __shared__ int sh[256];
    int t = threadIdx.x;
    int i = blockIdx.x * 256 + t;
    int v = (i < N_NODES) ? g_cnt_i[i] : 0;
    sh[t] = v;
    __syncthreads();
    for (int o = 1; o < 256; o <<= 1) {
        int tmp = (t >= o) ? sh[t - o] : 0;
        __syncthreads();
        sh[t] += tmp;
        __syncthreads();
    }
    if (i < N_NODES) g_rs[i] = g_bsum[blockIdx.x] + sh[t] - v;
}

__global__ void k_fill(const int* __restrict__ src, const int* __restrict__ dst, int E) {
    int e = blockIdx.x * blockDim.x + threadIdx.x;
    if (e >= E) return;
    int d = dst[e];
    int pos = g_rs[d] + atomicAdd(&g_fill[d], 1);
    g_csr[pos] = src[e];
}

// ---------------- CSR mean-aggregate: half-warp per node, fp16 gather ----------------
__global__ void k_agg() {
    int hw = (blockIdx.x * blockDim.x + threadIdx.x) >> 4;   // node
    int l  = threadIdx.x & 15;                               // 8 halves each
    if (hw >= N_NODES) return;
    int rs0 = g_rs[hw], rs1 = g_rs[hw + 1];
    float acc[8] = {0.f, 0.f, 0.f, 0.f, 0.f, 0.f, 0.f, 0.f};
    for (int e = rs0; e < rs1; e++) {
        int s = g_csr[e];
        uint4 u = *(const uint4*)(g_xh + (size_t)s * 128 + l * 8);
        float2 f;
        f = __half22float2(*(__half2*)&u.x); acc[0] += f.x; acc[1] += f.y;
        f = __half22float2(*(__half2*)&u.y); acc[2] += f.x; acc[3] += f.y;
        f = __half22float2(*(__half2*)&u.z); acc[4] += f.x; acc[5] += f.y;
        f = __half22float2(*(__half2*)&u.w); acc[6] += f.x; acc[7] += f.y;
    }
    float inv = 1.0f / fmaxf((float)(rs1 - rs0), 1.0f);
    __half2 p0 = __halves2half2(__float2half(acc[0] * inv), __float2half(acc[1] * inv));
    __half2 p1 = __halves2half2(__float2half(acc[2] * inv), __float2half(acc[3] * inv));
    __half2 p2 = __halves2half2(__float2half(acc[4] * inv), __float2half(acc[5] * inv));
    __half2 p3 = __halves2half2(__float2half(acc[6] * inv), __float2half(acc[7] * inv));
    uint4 o;
    o.x = *(uint32_t*)&p0; o.y = *(uint32_t*)&p1;
    o.z = *(uint32_t*)&p2; o.w = *(uint32_t*)&p3;
    *(uint4*)(g_aggh + (size_t)hw * 128 + l * 8) = o;
}

// ---------------- HMMA GEMM: fp16 single-term, all-cp.async, M=64 x N=256 ----------------
__global__ void __launch_bounds__(256, 2) k_gemm(const float* __restrict__ b1,
                                                 const float* __restrict__ W2l,
                                                 const float* __restrict__ W2r) {
    extern __shared__ char smem[];
    const int t    = threadIdx.x;
    const int lane = t & 31;
    const int wid  = t >> 5;
    const int wm   = wid >> 2;        // 0..1 (m strip of 32)
    const int wn   = wid & 3;         // 0..3 (n strip of 64)
    const int n0   = blockIdx.x * 64;

    float* sW2   = (float*)(smem + OFF_W2);
    float* sB1   = (float*)(smem + OFF_B1);
    float* sNorm = (float*)(smem + OFF_NORM);
    float* sZ    = (float*)(smem + OFF_Z);

    const uint32_t smb = smem_u32(smem);

    // ---- cp.async issue lambdas ----
    const int arow = t >> 2, aseg = t & 3;                  // A: 64 rows x 4 segs of 16B
    auto issueA = [&](int kc, uint32_t ah_off) {
        const __half* s = (kc < 128)
            ? g_aggh + (size_t)(n0 + arow) * 128 + kc + aseg * 8
            : g_xh   + (size_t)(n0 + arow) * 128 + (kc - 128) + aseg * 8;
        cp16(smb + ah_off + (uint32_t)(arow * 80 + aseg * 16), s);
    };
    const int bbr = t >> 2, bbc = t & 3;
    auto issueB = [&](int kc, uint32_t bh_off) {
#pragma unroll
        for (int i = 0; i < 4; i++) {
            int br = bbr + i * 64;
            uint32_t doff = (uint32_t)(br * 80 + bbc * 16);
            cp16(smb + bh_off + doff, g_Whf + (size_t)br * 256 + kc + bbc * 8);
        }
    };

    // prologue copies overlap epilogue-constant staging
    issueA(0, AH_OFF(0));
    issueB(0, BH_OFF(0));
    CP_COMMIT();

    sB1[t] = b1[t];
    for (int i = t; i < 1024; i += 256) {
        int m = i >> 8, k = i & 255;
        sW2[i] = (m < 2) ? W2l[m * 256 + k] : W2r[(m - 2) * 256 + k];
    }
    if (t < 64) {
        sNorm[t] = 0.f;
        ((float4*)sZ)[t] = make_float4(0.f, 0.f, 0.f, 0.f);
    }
    CP_WAIT0();
    __syncthreads();

    const uint32_t rowo = (lane & 7) + ((lane >> 3) & 1) * 8;
    const uint32_t kB   = (lane >> 4) * 16;
    const uint32_t aBase = smb + (wm * 32 + rowo) * 80 + kB;
    const uint32_t bBase = smb + (wn * 64 + rowo) * 80 + kB;

    float acc[2][8][4];
#pragma unroll
    for (int a = 0; a < 2; a++)
#pragma unroll
        for (int b = 0; b < 8; b++)
#pragma unroll
            for (int c = 0; c < 4; c++) acc[a][b][c] = 0.f;

    auto compute = [&](uint32_t ah_off, uint32_t bh_off) {
#pragma unroll
        for (int s = 0; s < 2; s++) {
            const uint32_t so = s * 32;
            uint32_t ah[2][4];
            ldsm_x4(ah[0], aBase + so + ah_off);
            ldsm_x4(ah[1], aBase + 16 * 80 + so + ah_off);
            uint32_t bh[4][4];
#pragma unroll
            for (int tp = 0; tp < 4; tp++)
                ldsm_x4(bh[tp], bBase + tp * (16 * 80) + so + bh_off);

#pragma unroll
            for (int tp = 0; tp < 4; tp++)
#pragma unroll
                for (int tm = 0; tm < 2; tm++) {
                    mma_f16(acc[tm][2 * tp],     ah[tm], bh[tp][0], bh[tp][2]);
                    mma_f16(acc[tm][2 * tp + 1], ah[tm], bh[tp][1], bh[tp][3]);
                }
        }
    };

    // ---- pipelined main loop: 8 chunks of K=32 ----
#pragma unroll
    for (int kci = 0; kci < 8; kci++) {
        const uint32_t cur = kci & 1, nxt = cur ^ 1;
        if (kci < 7) {
            issueA((kci + 1) * 32, AH_OFF(nxt));
            issueB((kci + 1) * 32, BH_OFF(nxt));
            CP_COMMIT();
        }
        compute(AH_OFF(cur), BH_OFF(cur));
        if (kci < 7) CP_WAIT0();
        __syncthreads();
    }

    // ---- epilogue ----
#pragma unroll
    for (int tm = 0; tm < 2; tm++) {
        float s0 = 0.f, s1 = 0.f;
#pragma unroll
        for (int tn = 0; tn < 8; tn++) {
            int c0 = wn * 64 + tn * 8 + (lane & 3) * 2;
            float b0v = sB1[c0], b1v = sB1[c0 + 1];
            acc[tm][tn][0] += b0v;
            acc[tm][tn][1] += b1v;
            acc[tm][tn][2] += b0v;
            acc[tm][tn][3] += b1v;
            s0 += acc[tm][tn][0] * acc[tm][tn][0] + acc[tm][tn][1] * acc[tm][tn][1];
            s1 += acc[tm][tn][2] * acc[tm][tn][2] + acc[tm][tn][3] * acc[tm][tn][3];
        }
        s0 += __shfl_xor_sync(0xffffffffu, s0, 1);
        s0 += __shfl_xor_sync(0xffffffffu, s0, 2);
        s1 += __shfl_xor_sync(0xffffffffu, s1, 1);
        s1 += __shfl_xor_sync(0xffffffffu, s1, 2);
        if ((lane & 3) == 0) {
            int r = wm * 32 + tm * 16 + (lane >> 2);
            atomicAdd(&sNorm[r], s0);
            atomicAdd(&sNorm[r + 8], s1);
        }
    }
    __syncthreads();
    if (t < 64) sNorm[t] = 1.0f / fmaxf(sqrtf(sNorm[t]), 1e-12f);
    __syncthreads();

#pragma unroll
    for (int tm = 0; tm < 2; tm++) {
        int rbase = wm * 32 + tm * 16 + (lane >> 2);
        float rc0 = sNorm[rbase], rc1 = sNorm[rbase + 8];
        float d0[4] = {0.f, 0.f, 0.f, 0.f};
        float d1[4] = {0.f, 0.f, 0.f, 0.f};
#pragma unroll
        for (int tn = 0; tn < 8; tn++) {
            int c0 = wn * 64 + tn * 8 + (lane & 3) * 2;
            float h00 = fmaxf(acc[tm][tn][0] * rc0, 0.f);
            float h01 = fmaxf(acc[tm][tn][1] * rc0, 0.f);
            float h10 = fmaxf(acc[tm][tn][2] * rc1, 0.f);
            float h11 = fmaxf(acc[tm][tn][3] * rc1, 0.f);
#pragma unroll
            for (int o = 0; o < 4; o++) {
                float w0 = sW2[o * 256 + c0], w1 = sW2[o * 256 + c0 + 1];
                d0[o] += h00 * w0 + h01 * w1;
                d1[o] += h10 * w0 + h11 * w1;
            }
        }
#pragma unroll
        for (int o = 0; o < 4; o++) {
            d0[o] += __shfl_xor_sync(0xffffffffu, d0[o], 1);
            d0[o] += __shfl_xor_sync(0xffffffffu, d0[o], 2);
            d1[o] += __shfl_xor_sync(0xffffffffu, d1[o], 1);
            d1[o] += __shfl_xor_sync(0xffffffffu, d1[o], 2);
        }
        if ((lane & 3) == 0) {
#pragma unroll
            for (int o = 0; o < 4; o++) {
                atomicAdd(&sZ[rbase * 4 + o], d0[o]);
                atomicAdd(&sZ[(rbase + 8) * 4 + o], d1[o]);
            }
        }
    }
    __syncthreads();
    if (t < 64) {
        int n = n0 + t;
        if (n < N_NODES) {
            g_zl[n] = make_float2(sZ[t * 4 + 0], sZ[t * 4 + 1]);
            g_zr[n] = make_float2(sZ[t * 4 + 2], sZ[t * 4 + 3]);
        }
    }
}

// ---------------- scatter layer 2 + final ----------------
__global__ void k_scatter2(const int* __restrict__ src,
                           const int* __restrict__ dst, int E) {
    int e = blockIdx.x * blockDim.x + threadIdx.x;
    if (e >= E) return;
    int s = src[e];
    int d = dst[e];
    float2 z = g_zl[s];
    asm volatile("red.global.add.v2.f32 [%0], {%1, %2};"
                 :: "l"(&g_agg2s[d]), "f"(z.x), "f"(z.y) : "memory");
}

__global__ void k_final(const float* __restrict__ b2, float* __restrict__ out) {
    int n = blockIdx.x * blockDim.x + threadIdx.x;
    if (n >= N_NODES) return;
    float inv = 1.0f / fmaxf((float)(g_rs[n + 1] - g_rs[n]), 1.0f);
    float2 a = g_agg2s[n];
    float2 r = g_zr[n];
    float v0 = a.x * inv + r.x + b2[0];
    float v1 = a.y * inv + r.y + b2[1];
    float s = 1.0f / fmaxf(sqrtf(v0 * v0 + v1 * v1), 1e-12f);
    v0 *= s; v1 *= s;
    float m = fmaxf(v0, v1);
    float l = m + logf(expf(v0 - m) + expf(v1 - m));
    out[(size_t)n * 2 + 0] = v0 - l;
    out[(size_t)n * 2 + 1] = v1 - l;
}

extern "C" void kernel_launch(void* const* d_in, const int* in_sizes, int n_in,
                              void* d_out, int out_size) {
    const float* x   = (const float*)d_in[0];
    const int*   ei  = (const int*)d_in[1];
    const float* W1l = (const float*)d_in[2];
    const float* b1  = (const float*)d_in[3];
    const float* W1r = (const float*)d_in[4];
    const float* W2l = (const float*)d_in[5];
    const float* b2  = (const float*)d_in[6];
    const float* W2r = (const float*)d_in[7];
    float*       out = (float*)d_out;

    int E = in_sizes[1] / 2;
    if (E > E_MAX) E = E_MAX;
    const int* src = ei;
    const int* dst = ei + E;

    cudaFuncSetAttribute(k_gemm, cudaFuncAttributeMaxDynamicSharedMemorySize, SMEM_DYN);

    k_zero0<<<98, 1024>>>();
    k_prep<<<592, 256>>>(x, W1l, W1r);
    k_count<<<(E + 255) / 256, 256>>>(dst, E);
    k_scan1<<<NBLK, 256>>>();
    k_scan2<<<1, 512>>>();
    k_scan3<<<NBLK, 256>>>();
    k_fill<<<(E + 255) / 256, 256>>>(src, dst, E);
    k_agg<<<(N_NODES * 16 + 255) / 256, 256>>>();
    k_gemm<<<N_TILES, 256, SMEM_DYN>>>(b1, W2l, W2r);
    k_scatter2<<<(E + 255) / 256, 256>>>(src, dst, E);
    k_final<<<(N_NODES + 255) / 256, 256>>>(b2, out);
}

// round 17
// speedup vs baseline: 1.5233x; 1.0478x over previous
#include <cuda_runtime.h>
#include <cuda_fp16.h>
#include <math.h>
#include <stdint.h>

#define N_NODES 100000
#define N_PAD   100032
#define E_MAX   600000
#define N_TILES 782    // ceil(100000/128)
#define GRID_P  148
#define NBLK    391    // ceil(100000/256)

// ---------------- scratch (static device globals) ----------------
__device__ int    g_cnt_i[N_NODES];
__device__ int    g_fill [N_NODES];
__device__ int    g_rs   [N_NODES + 1];
__device__ int    g_csr  [E_MAX];
__device__ int    g_bsum [512];
__device__ float2 g_zl   [N_NODES];
__device__ float2 g_zr   [N_NODES];
__device__ float2 g_agg2s[N_NODES];
__device__ __half g_xh  [(size_t)N_PAD * 128];   // x in fp16 (pad rows stay 0)
__device__ __half g_aggh[(size_t)N_PAD * 128];   // mean-agg, fp16
__device__ __half g_Whf [256 * 256];             // W[n=256][k=256] fp16

// ---------------- helpers ----------------
__device__ __forceinline__ uint32_t smem_u32(const void* p) {
    uint32_t a;
    asm("{ .reg .u64 t; cvta.to.shared.u64 t, %1; cvt.u32.u64 %0, t; }" : "=r"(a) : "l"(p));
    return a;
}
__device__ __forceinline__ void ldsm_x4(uint32_t* r, uint32_t addr) {
    asm volatile("ldmatrix.sync.aligned.m8n8.x4.shared.b16 {%0,%1,%2,%3}, [%4];"
                 : "=r"(r[0]), "=r"(r[1]), "=r"(r[2]), "=r"(r[3]) : "r"(addr));
}
__device__ __forceinline__ void mma_f16(float* d, const uint32_t* a, uint32_t b0, uint32_t b1) {
    asm volatile("mma.sync.aligned.m16n8k16.row.col.f32.f16.f16.f32 "
                 "{%0,%1,%2,%3}, {%4,%5,%6,%7}, {%8,%9}, {%0,%1,%2,%3};"
                 : "+f"(d[0]), "+f"(d[1]), "+f"(d[2]), "+f"(d[3])
                 : "r"(a[0]), "r"(a[1]), "r"(a[2]), "r"(a[3]), "r"(b0), "r"(b1));
}
__device__ __forceinline__ void cp16(uint32_t sm, const void* g) {
    asm volatile("cp.async.cg.shared.global [%0], [%1], 16;" :: "r"(sm), "l"(g));
}
#define CP_COMMIT() asm volatile("cp.async.commit_group;" ::: "memory")
#define CP_WAIT0()  asm volatile("cp.async.wait_group 0;" ::: "memory")

// ---------------- SMEM map (persistent gemm) ----------------
// W resident: 4 kblocks of 32KB, each [256 rows][128B], SW128 swizzled
#define WHI_OFF     0u
#define A_OFF(st)   (131072u + (st) * 10240u)   // 128 rows * 80B, 2 stages
#define OFF_W2      151552u   // 4*256 f32
#define OFF_B1      155648u   // 256 f32
#define OFF_NORM    156672u   // 128 f32
#define OFF_Z       157184u   // 128*4 f32
#define SMEM_DYN    159232

// ---------------- prep kernels ----------------
__global__ void k_zero0() {
    int i = blockIdx.x * blockDim.x + threadIdx.x;
    int stride = gridDim.x * blockDim.x;
    for (int n = i; n < N_NODES; n += stride) {
        g_cnt_i[n] = 0;
        g_fill[n] = 0;
        g_agg2s[n] = make_float2(0.f, 0.f);
    }
}

__global__ void k_prep(const float* __restrict__ x,
                       const float* __restrict__ W1l, const float* __restrict__ W1r) {
    int i = blockIdx.x * blockDim.x + threadIdx.x;
    int stride = gridDim.x * blockDim.x;
    const int XQ = N_NODES * 32;
    for (int q = i; q < XQ; q += stride) {
        float4 v = ((const float4*)x)[q];
        __half2 p0 = __halves2half2(__float2half(v.x), __float2half(v.y));
        __half2 p1 = __halves2half2(__float2half(v.z), __float2half(v.w));
        uint2 u; u.x = *(uint32_t*)&p0; u.y = *(uint32_t*)&p1;
        ((uint2*)g_xh)[q] = u;
    }
    for (int q = i; q < 256 * 256; q += stride) {
        int h = q >> 8, k = q & 255;
        float v = (k < 128) ? W1l[h * 128 + k] : W1r[h * 128 + (k - 128)];
        g_Whf[q] = __float2half(v);
    }
}

__global__ void k_count(const int* __restrict__ dst, int E) {
    int e = blockIdx.x * blockDim.x + threadIdx.x;
    if (e < E) atomicAdd(&g_cnt_i[dst[e]], 1);
}

__global__ void k_scan1() {
    __shared__ int sh[256];
    int t = threadIdx.x;
    int i = blockIdx.x * 256 + t;
    sh[t] = (i < N_NODES) ? g_cnt_i[i] : 0;
    __syncthreads();
    for (int o = 128; o > 0; o >>= 1) {
        if (t < o) sh[t] += sh[t + o];
        __syncthreads();
    }
    if (t == 0) g_bsum[blockIdx.x] = sh[0];
}

__global__ void k_scan2() {
    __shared__ int sh[512];
    int t = threadIdx.x;
    int v = (t < NBLK) ? g_bsum[t] : 0;
    sh[t] = v;
    __syncthreads();
    for (int o = 1; o < 512; o <<= 1) {
        int tmp = (t >= o) ? sh[t - o] : 0;
        __syncthreads();
        sh[t] += tmp;
        __syncthreads();
    }
    if (t < NBLK) g_bsum[t] = sh[t] - v;   // exclusive
    if (t == NBLK - 1) g_rs[N_NODES] = sh[t];
}

__global__ void k_scan3() {
    __shared__ int sh[256];
    int t = threadIdx.x;
    int i = blockIdx.x * 256 + t;
    int v = (i < N_NODES) ? g_cnt_i[i] : 0;
    sh[t] = v;
    __syncthreads();
    for (int o = 1; o < 256; o <<= 1) {
        int tmp = (t >= o) ? sh[t - o] : 0;
        __syncthreads();
        sh[t] += tmp;
        __syncthreads();
    }
    if (i < N_NODES) g_rs[i] = g_bsum[blockIdx.x] + sh[t] - v;
}

__global__ void k_fill(const int* __restrict__ src, const int* __restrict__ dst, int E) {
    int e = blockIdx.x * blockDim.x + threadIdx.x;
    if (e >= E) return;
    int d = dst[e];
    int pos = g_rs[d] + atomicAdd(&g_fill[d], 1);
    g_csr[pos] = src[e];
}

// ---------------- CSR mean-aggregate: half-warp per node, fp16 gather ----------------
__global__ void k_agg() {
    int hw = (blockIdx.x * blockDim.x + threadIdx.x) >> 4;
    int l  = threadIdx.x & 15;
    if (hw >= N_NODES) return;
    int rs0 = g_rs[hw], rs1 = g_rs[hw + 1];
    float acc[8] = {0.f, 0.f, 0.f, 0.f, 0.f, 0.f, 0.f, 0.f};
    for (int e = rs0; e < rs1; e++) {
        int s = g_csr[e];
        uint4 u = *(const uint4*)(g_xh + (size_t)s * 128 + l * 8);
        float2 f;
        f = __half22float2(*(__half2*)&u.x); acc[0] += f.x; acc[1] += f.y;
        f = __half22float2(*(__half2*)&u.y); acc[2] += f.x; acc[3] += f.y;
        f = __half22float2(*(__half2*)&u.z); acc[4] += f.x; acc[5] += f.y;
        f = __half22float2(*(__half2*)&u.w); acc[6] += f.x; acc[7] += f.y;
    }
    float inv = 1.0f / fmaxf((float)(rs1 - rs0), 1.0f);
    __half2 p0 = __halves2half2(__float2half(acc[0] * inv), __float2half(acc[1] * inv));
    __half2 p1 = __halves2half2(__float2half(acc[2] * inv), __float2half(acc[3] * inv));
    __half2 p2 = __halves2half2(__float2half(acc[4] * inv), __float2half(acc[5] * inv));
    __half2 p3 = __halves2half2(__float2half(acc[6] * inv), __float2half(acc[7] * inv));
    uint4 o;
    o.x = *(uint32_t*)&p0; o.y = *(uint32_t*)&p1;
    o.z = *(uint32_t*)&p2; o.w = *(uint32_t*)&p3;
    *(uint4*)(g_aggh + (size_t)hw * 128 + l * 8) = o;
}

// ---------------- persistent HMMA GEMM: W resident, M=128, N=256, 512 thr ----------------
__global__ void __launch_bounds__(512, 1) k_gemm(const float* __restrict__ b1,
                                                 const float* __restrict__ W2l,
                                                 const float* __restrict__ W2r) {
    extern __shared__ char smem[];
    const int t    = threadIdx.x;
    const int lane = t & 31;
    const int wid  = t >> 5;
    const int wm   = wid >> 2;        // 0..3 (m strip of 32)
    const int wn   = wid & 3;         // 0..3 (n strip of 64)

    float* sW2   = (float*)(smem + OFF_W2);
    float* sB1   = (float*)(smem + OFF_B1);
    float* sNorm = (float*)(smem + OFF_NORM);
    float* sZ    = (float*)(smem + OFF_Z);

    const uint32_t smb = smem_u32(smem);

    // ---- one-time: resident swizzled W + epilogue constants ----
#pragma unroll
    for (int i = 0; i < 16; i++) {
        int idx  = t + i * 512;           // 0..8191 (8192 x 16B = 128KB)
        int kblk = idx >> 11;             // 0..3
        int rr   = (idx >> 3) & 255;
        int kb   = idx & 7;
        uint32_t off = (uint32_t)(rr * 128 + kb * 16);
        uint32_t sw  = off ^ ((off >> 3) & 0x70);
        cp16(smb + WHI_OFF + (uint32_t)kblk * 32768u + sw,
             g_Whf + (size_t)rr * 256 + kblk * 64 + kb * 8);
    }
    CP_COMMIT();
    for (int i = t; i < 256; i += 512) sB1[i] = b1[i];
    for (int i = t; i < 1024; i += 512) {
        int m = i >> 8, k = i & 255;
        sW2[i] = (m < 2) ? W2l[m * 256 + k] : W2r[(m - 2) * 256 + k];
    }
    CP_WAIT0();
    __syncthreads();

    // ---- per-warp constants ----
    const uint32_t rowo = (lane & 7) + ((lane >> 3) & 1) * 8;
    const uint32_t kB   = (lane >> 4) * 16;
    const uint32_t aRel = (wm * 32 + rowo) * 80 + kB;
    uint32_t bBase[4], xorv[4];
#pragma unroll
    for (int tp = 0; tp < 4; tp++) {
        uint32_t row = wn * 64 + tp * 16 + rowo;
        bBase[tp] = smb + WHI_OFF + row * 128;
        xorv[tp]  = (row & 7) << 4;
    }

    // A copy geometry: 128 rows x 2 segs of 16B per chunk (512 cp16)
    const int arow = t >> 2, aseg = t & 3;
    auto issueA = [&](int n0, int kc, uint32_t a_off) {
        const __half* s = (kc < 128)
            ? g_aggh + (size_t)(n0 + arow) * 128 + kc + aseg * 8
            : g_xh   + (size_t)(n0 + arow) * 128 + (kc - 128) + aseg * 8;
        cp16(smb + a_off + (uint32_t)(arow * 80 + aseg * 16), s);
    };

    // ---- persistent tile loop ----
    for (int tile = blockIdx.x; tile < N_TILES; tile += GRID_P) {
        const int n0 = tile * 128;

        if (t < 128) {
            sNorm[t] = 0.f;
            ((float4*)sZ)[t] = make_float4(0.f, 0.f, 0.f, 0.f);
        }

        float acc[2][8][4];
#pragma unroll
        for (int a = 0; a < 2; a++)
#pragma unroll
            for (int b = 0; b < 8; b++)
#pragma unroll
                for (int c = 0; c < 4; c++) acc[a][b][c] = 0.f;

        issueA(n0, 0, A_OFF(0));
        CP_COMMIT();
        CP_WAIT0();
        __syncthreads();

        auto compute = [&](int c, uint32_t a_off) {
            const uint32_t kblkOff = (uint32_t)(c >> 1) * 32768u;
            const uint32_t cHalf   = (uint32_t)(c & 1) * 64u;
#pragma unroll
            for (int s = 0; s < 2; s++) {
                const uint32_t so = s * 32;
                uint32_t ah[2][4];
                ldsm_x4(ah[0], smb + a_off + aRel + so);
                ldsm_x4(ah[1], smb + a_off + aRel + 16 * 80 + so);
                const uint32_t sbyte = cHalf + so + kB;
                uint32_t bh[4][4];
#pragma unroll
                for (int tp = 0; tp < 4; tp++)
                    ldsm_x4(bh[tp], bBase[tp] + kblkOff + (sbyte ^ xorv[tp]));

#pragma unroll
                for (int tp = 0; tp < 4; tp++)
#pragma unroll
                    for (int tm = 0; tm < 2; tm++) {
                        mma_f16(acc[tm][2 * tp],     ah[tm], bh[tp][0], bh[tp][2]);
                        mma_f16(acc[tm][2 * tp + 1], ah[tm], bh[tp][1], bh[tp][3]);
                    }
            }
        };

        // ---- chunks: A double-buffered, W resident ----
#pragma unroll
        for (int kci = 0; kci < 8; kci++) {
            const uint32_t cur = kci & 1, nxt = cur ^ 1;
            if (kci < 7) {
                issueA(n0, (kci + 1) * 32, A_OFF(nxt));
                CP_COMMIT();
            }
            compute(kci, A_OFF(cur));
            if (kci < 7) CP_WAIT0();
            __syncthreads();
        }

        // ---- epilogue ----
#pragma unroll
        for (int tm = 0; tm < 2; tm++) {
            float s0 = 0.f, s1 = 0.f;
#pragma unroll
            for (int tn = 0; tn < 8; tn++) {
                int c0 = wn * 64 + tn * 8 + (lane & 3) * 2;
                float b0v = sB1[c0], b1v = sB1[c0 + 1];
                acc[tm][tn][0] += b0v;
                acc[tm][tn][1] += b1v;
                acc[tm][tn][2] += b0v;
                acc[tm][tn][3] += b1v;
                s0 += acc[tm][tn][0] * acc[tm][tn][0] + acc[tm][tn][1] * acc[tm][tn][1];
                s1 += acc[tm][tn][2] * acc[tm][tn][2] + acc[tm][tn][3] * acc[tm][tn][3];
            }
            s0 += __shfl_xor_sync(0xffffffffu, s0, 1);
            s0 += __shfl_xor_sync(0xffffffffu, s0, 2);
            s1 += __shfl_xor_sync(0xffffffffu, s1, 1);
            s1 += __shfl_xor_sync(0xffffffffu, s1, 2);
            if ((lane & 3) == 0) {
                int r = wm * 32 + tm * 16 + (lane >> 2);
                atomicAdd(&sNorm[r], s0);
                atomicAdd(&sNorm[r + 8], s1);
            }
        }
        __syncthreads();
        if (t < 128) sNorm[t] = 1.0f / fmaxf(sqrtf(sNorm[t]), 1e-12f);
        __syncthreads();

#pragma unroll
        for (int tm = 0; tm < 2; tm++) {
            int rbase = wm * 32 + tm * 16 + (lane >> 2);
            float rc0 = sNorm[rbase], rc1 = sNorm[rbase + 8];
            float d0[4] = {0.f, 0.f, 0.f, 0.f};
            float d1[4] = {0.f, 0.f, 0.f, 0.f};
#pragma unroll
            for (int tn = 0; tn < 8; tn++) {
                int c0 = wn * 64 + tn * 8 + (lane & 3) * 2;
                float h00 = fmaxf(acc[tm][tn][0] * rc0, 0.f);
                float h01 = fmaxf(acc[tm][tn][1] * rc0, 0.f);
                float h10 = fmaxf(acc[tm][tn][2] * rc1, 0.f);
                float h11 = fmaxf(acc[tm][tn][3] * rc1, 0.f);
#pragma unroll
                for (int o = 0; o < 4; o++) {
                    float w0 = sW2[o * 256 + c0], w1 = sW2[o * 256 + c0 + 1];
                    d0[o] += h00 * w0 + h01 * w1;
                    d1[o] += h10 * w0 + h11 * w1;
                }
            }
#pragma unroll
            for (int o = 0; o < 4; o++) {
                d0[o] += __shfl_xor_sync(0xffffffffu, d0[o], 1);
                d0[o] += __shfl_xor_sync(0xffffffffu, d0[o], 2);
                d1[o] += __shfl_xor_sync(0xffffffffu, d1[o], 1);
                d1[o] += __shfl_xor_sync(0xffffffffu, d1[o], 2);
            }
            if ((lane & 3) == 0) {
#pragma unroll
                for (int o = 0; o < 4; o++) {
                    atomicAdd(&sZ[rbase * 4 + o], d0[o]);
                    atomicAdd(&sZ[(rbase + 8) * 4 + o], d1[o]);
                }
            }
        }
        __syncthreads();
        if (t < 128) {
            int n = n0 + t;
            if (n < N_NODES) {
                g_zl[n] = make_float2(sZ[t * 4 + 0], sZ[t * 4 + 1]);
                g_zr[n] = make_float2(sZ[t * 4 + 2], sZ[t * 4 + 3]);
            }
        }
        __syncthreads();
    }
}

// ---------------- scatter layer 2 + final ----------------
__global__ void k_scatter2(const int* __restrict__ src,
                           const int* __restrict__ dst, int E) {
    int e = blockIdx.x * blockDim.x + threadIdx.x;
    if (e >= E) return;
    int s = src[e];
    int d = dst[e];
    float2 z = g_zl[s];
    asm volatile("red.global.add.v2.f32 [%0], {%1, %2};"
                 :: "l"(&g_agg2s[d]), "f"(z.x), "f"(z.y) : "memory");
}

__global__ void k_final(const float* __restrict__ b2, float* __restrict__ out) {
    int n = blockIdx.x * blockDim.x + threadIdx.x;
    if (n >= N_NODES) return;
    float inv = 1.0f / fmaxf((float)(g_rs[n + 1] - g_rs[n]), 1.0f);
    float2 a = g_agg2s[n];
    float2 r = g_zr[n];
    float v0 = a.x * inv + r.x + b2[0];
    float v1 = a.y * inv + r.y + b2[1];
    float s = 1.0f / fmaxf(sqrtf(v0 * v0 + v1 * v1), 1e-12f);
    v0 *= s; v1 *= s;
    float m = fmaxf(v0, v1);
    float l = m + logf(expf(v0 - m) + expf(v1 - m));
    out[(size_t)n * 2 + 0] = v0 - l;
    out[(size_t)n * 2 + 1] = v1 - l;
}

extern "C" void kernel_launch(void* const* d_in, const int* in_sizes, int n_in,
                              void* d_out, int out_size) {
    const float* x   = (const float*)d_in[0];
    const int*   ei  = (const int*)d_in[1];
    const float* W1l = (const float*)d_in[2];
    const float* b1  = (const float*)d_in[3];
    const float* W1r = (const float*)d_in[4];
    const float* W2l = (const float*)d_in[5];
    const float* b2  = (const float*)d_in[6];
    const float* W2r = (const float*)d_in[7];
    float*       out = (float*)d_out;

    int E = in_sizes[1] / 2;
    if (E > E_MAX) E = E_MAX;
    const int* src = ei;
    const int* dst = ei + E;

    cudaFuncSetAttribute(k_gemm, cudaFuncAttributeMaxDynamicSharedMemorySize, SMEM_DYN);

    k_zero0<<<98, 1024>>>();
    k_prep<<<592, 256>>>(x, W1l, W1r);
    k_count<<<(E + 255) / 256, 256>>>(dst, E);
    k_scan1<<<NBLK, 256>>>();
    k_scan2<<<1, 512>>>();
    k_scan3<<<NBLK, 256>>>();
    k_fill<<<(E + 255) / 256, 256>>>(src, dst, E);
    k_agg<<<(N_NODES * 16 + 255) / 256, 256>>>();
    k_gemm<<<GRID_P, 512, SMEM_DYN>>>(b1, W2l, W2r);
    k_scatter2<<<(E + 255) / 256, 256>>>(src, dst, E);
    k_final<<<(N_NODES + 255) / 256, 256>>>(b2, out);
}